// round 6
// baseline (speedup 1.0000x reference)
#include <cuda_runtime.h>

#define TPB  128
#define NGPB 4        // groups (of 32 inputs) per block
#define CPT  2        // output columns per thread

// Coefficient table: 34 entries per group in piece order k=0..33.
// Piece value (masked bits as uint) == q * 2^s exactly; coeff = x[off] * KSCALE
// so fma gives q*x exactly after the exact magic-subtract.
__device__ const int KOFF[34] = {
    0,1, 2,3, 4,5, 6,7, 8,9, 10,10, 11,12, 13,14, 15,16, 17,18,
    19,20, 21,21, 22,23, 24,25, 26,27, 28,29, 30,31
};
__device__ const float KSCALE[34] = {
    0x1p0f, 0x1p-3f, 0x1p-6f, 0x1p-9f, 0x1p-12f, 0x1p-15f, 0x1p-18f,   // A fields j=0..6
    0x1p0f, 0x1p-3f, 0x1p-6f,                                          // B fields j=7..9 (r0>>21)
    0x1p-9f,                                                           // w10 lo (B bits 9-10)
    4.0f,                                                              // w10 hi (r1 bit 0)
    0x1p-1f, 0x1p-4f, 0x1p-7f, 0x1p-10f, 0x1p-13f, 0x1p-16f, 0x1p-19f, // C fields j=0..6
    0x1p0f, 0x1p-3f, 0x1p-6f,                                          // D fields j=7..9 (r1>>22)
    0x1p-9f,                                                           // w21 lo (D bit 9)
    2.0f,                                                              // w21 hi (r2 bits 0-1)
    0x1p-2f, 0x1p-5f, 0x1p-8f, 0x1p-11f, 0x1p-14f, 0x1p-17f, 0x1p-20f, // E fields j=0..6
    0x1p0f, 0x1p-3f, 0x1p-6f                                           // F fields j=7..9 (r2>>23)
};

// One piece: mask field in place, OR the 2^23 magic exponent (LOP3), bitcast,
// exact subtract of 2^23 (FADD), fma into accumulator. 3 instrs, no packing.
#define PIECE(acc, v, m, c) \
    acc = fmaf(__uint_as_float(((v) & (m)) | 0x4B000000u) - 8388608.0f, (c), acc)

// Process one 32-input group for TWO columns; coefficients via 9 x LDS.128.
__device__ __forceinline__ void dogroup(
    float& a00, float& a01, float& a10, float& a11,
    unsigned A0, unsigned C0, unsigned E0,
    unsigned A1, unsigned C1, unsigned E1,
    const float4* __restrict__ cp)
{
    unsigned B0 = A0 >> 21, D0 = C0 >> 22, F0 = E0 >> 23;
    unsigned B1 = A1 >> 21, D1 = C1 >> 22, F1 = E1 >> 23;
    float4 v;
    v = cp[0];
    PIECE(a00, A0, 0x00000007u, v.x);  PIECE(a10, A1, 0x00000007u, v.x);
    PIECE(a01, A0, 0x00000038u, v.y);  PIECE(a11, A1, 0x00000038u, v.y);
    PIECE(a00, A0, 0x000001C0u, v.z);  PIECE(a10, A1, 0x000001C0u, v.z);
    PIECE(a01, A0, 0x00000E00u, v.w);  PIECE(a11, A1, 0x00000E00u, v.w);
    v = cp[1];
    PIECE(a00, A0, 0x00007000u, v.x);  PIECE(a10, A1, 0x00007000u, v.x);
    PIECE(a01, A0, 0x00038000u, v.y);  PIECE(a11, A1, 0x00038000u, v.y);
    PIECE(a00, A0, 0x001C0000u, v.z);  PIECE(a10, A1, 0x001C0000u, v.z);
    PIECE(a01, B0, 0x00000007u, v.w);  PIECE(a11, B1, 0x00000007u, v.w);
    v = cp[2];
    PIECE(a00, B0, 0x00000038u, v.x);  PIECE(a10, B1, 0x00000038u, v.x);
    PIECE(a01, B0, 0x000001C0u, v.y);  PIECE(a11, B1, 0x000001C0u, v.y);
    PIECE(a00, B0, 0x00000600u, v.z);  PIECE(a10, B1, 0x00000600u, v.z);
    PIECE(a01, C0, 0x00000001u, v.w);  PIECE(a11, C1, 0x00000001u, v.w);
    v = cp[3];
    PIECE(a00, C0, 0x0000000Eu, v.x);  PIECE(a10, C1, 0x0000000Eu, v.x);
    PIECE(a01, C0, 0x00000070u, v.y);  PIECE(a11, C1, 0x00000070u, v.y);
    PIECE(a00, C0, 0x00000380u, v.z);  PIECE(a10, C1, 0x00000380u, v.z);
    PIECE(a01, C0, 0x00001C00u, v.w);  PIECE(a11, C1, 0x00001C00u, v.w);
    v = cp[4];
    PIECE(a00, C0, 0x0000E000u, v.x);  PIECE(a10, C1, 0x0000E000u, v.x);
    PIECE(a01, C0, 0x00070000u, v.y);  PIECE(a11, C1, 0x00070000u, v.y);
    PIECE(a00, C0, 0x00380000u, v.z);  PIECE(a10, C1, 0x00380000u, v.z);
    PIECE(a01, D0, 0x00000007u, v.w);  PIECE(a11, D1, 0x00000007u, v.w);
    v = cp[5];
    PIECE(a00, D0, 0x00000038u, v.x);  PIECE(a10, D1, 0x00000038u, v.x);
    PIECE(a01, D0, 0x000001C0u, v.y);  PIECE(a11, D1, 0x000001C0u, v.y);
    PIECE(a00, D0, 0x00000200u, v.z);  PIECE(a10, D1, 0x00000200u, v.z);
    PIECE(a01, E0, 0x00000003u, v.w);  PIECE(a11, E1, 0x00000003u, v.w);
    v = cp[6];
    PIECE(a00, E0, 0x0000001Cu, v.x);  PIECE(a10, E1, 0x0000001Cu, v.x);
    PIECE(a01, E0, 0x000000E0u, v.y);  PIECE(a11, E1, 0x000000E0u, v.y);
    PIECE(a00, E0, 0x00000700u, v.z);  PIECE(a10, E1, 0x00000700u, v.z);
    PIECE(a01, E0, 0x00003800u, v.w);  PIECE(a11, E1, 0x00003800u, v.w);
    v = cp[7];
    PIECE(a00, E0, 0x0001C000u, v.x);  PIECE(a10, E1, 0x0001C000u, v.x);
    PIECE(a01, E0, 0x000E0000u, v.y);  PIECE(a11, E1, 0x000E0000u, v.y);
    PIECE(a00, E0, 0x00700000u, v.z);  PIECE(a10, E1, 0x00700000u, v.z);
    PIECE(a01, F0, 0x00000007u, v.w);  PIECE(a11, F1, 0x00000007u, v.w);
    v = cp[8];
    PIECE(a00, F0, 0x00000038u, v.x);  PIECE(a10, F1, 0x00000038u, v.x);
    PIECE(a01, F0, 0x000001C0u, v.y);  PIECE(a11, F1, 0x000001C0u, v.y);
}

// Fused kernel: every block accumulates its K-chunk of the quantized GEMV into
// out via atomicAdd. blockIdx.y==0 blocks additionally fold in
// bias - zeros*sum(x) + oweight @ x[outlieridx] for their columns.
// out must be zeroed before launch (cudaMemsetAsync).
__global__ __launch_bounds__(TPB, 16)
void k_fused(const float* __restrict__ x,
             const int*   __restrict__ qw,
             const float* __restrict__ scales,
             const float* __restrict__ zeros,
             const float* __restrict__ bias,
             const float* __restrict__ oweight,
             const int*   __restrict__ outlieridx,
             float* __restrict__ out,
             int OUTF, int INF, int NOUT)
{
    __shared__ __align__(16) float cs[NGPB * 36];
    __shared__ float wred[TPB / 32];
    __shared__ float xo[64];

    const int tid = threadIdx.x;
    const int gbase = blockIdx.y * NGPB;
    const int colbase = blockIdx.x * (TPB * CPT) + tid * CPT;
    const bool doconst = (blockIdx.y == 0);

    if (doconst) {
        // block-wide sum(x) + gather outlier x values
        float s = 0.f;
        const float4* x4 = (const float4*)x;
        for (int i = tid; i < INF / 4; i += TPB) {
            float4 v = x4[i];
            s += (v.x + v.y) + (v.z + v.w);
        }
        #pragma unroll
        for (int d = 16; d > 0; d >>= 1) s += __shfl_xor_sync(0xFFFFFFFFu, s, d);
        if ((tid & 31) == 0) wred[tid >> 5] = s;
        if (tid < NOUT) xo[tid] = x[outlieridx[tid]];
    }

    // Build prescaled coefficient table for this K-chunk (pad entries zeroed).
    for (int idx = tid; idx < NGPB * 36; idx += TPB) {
        int g = idx / 36, k = idx - g * 36;
        float v = 0.f;
        if (k < 34) v = x[(gbase + g) * 32 + KOFF[k]] * KSCALE[k];
        cs[idx] = v;
    }
    __syncthreads();

    const int rowstride2 = OUTF / 2;  // int2 stride between qweight rows

    float a00 = 0.f, a01 = 0.f, a10 = 0.f, a11 = 0.f;

    const int2* row = (const int2*)(qw + (long)gbase * 3 * OUTF + colbase);

    // prefetch group 0 weights
    int2 w0 = row[0];
    int2 w1 = row[rowstride2];
    int2 w2 = row[2 * rowstride2];

    #pragma unroll
    for (int g = 0; g < NGPB; ++g) {
        int2 n0, n1, n2;
        if (g + 1 < NGPB) {
            const int2* nrow = row + 3 * rowstride2;
            n0 = nrow[0];
            n1 = nrow[rowstride2];
            n2 = nrow[2 * rowstride2];
            row = nrow;
        }

        const float4* cp = (const float4*)&cs[g * 36];
        dogroup(a00, a01, a10, a11,
                (unsigned)w0.x, (unsigned)w1.x, (unsigned)w2.x,
                (unsigned)w0.y, (unsigned)w1.y, (unsigned)w2.y,
                cp);

        w0 = n0; w1 = n1; w2 = n2;
    }

    const int o0 = colbase, o1 = colbase + 1;

    float base0 = 0.f, base1 = 0.f;
    if (doconst) {
        const float sumx = wred[0] + wred[1] + wred[2] + wred[3];
        base0 = bias[o0] - zeros[o0] * sumx;
        base1 = bias[o1] - zeros[o1] * sumx;
        const float4* ow0 = (const float4*)(oweight + (size_t)o0 * NOUT);
        const float4* ow1 = (const float4*)(oweight + (size_t)o1 * NOUT);
        #pragma unroll 8
        for (int j = 0; j < NOUT / 4; ++j) {
            float4 u = ow0[j];
            float4 v = ow1[j];
            float q0 = xo[4 * j + 0], q1 = xo[4 * j + 1];
            float q2 = xo[4 * j + 2], q3 = xo[4 * j + 3];
            base0 = fmaf(u.x, q0, base0);
            base1 = fmaf(v.x, q0, base1);
            base0 = fmaf(u.y, q1, base0);
            base1 = fmaf(v.y, q1, base1);
            base0 = fmaf(u.z, q2, base0);
            base1 = fmaf(v.z, q2, base1);
            base0 = fmaf(u.w, q3, base0);
            base1 = fmaf(v.w, q3, base1);
        }
    }

    atomicAdd(&out[o0], fmaf(scales[o0], a00 + a01, base0));
    atomicAdd(&out[o1], fmaf(scales[o1], a10 + a11, base1));
}

extern "C" void kernel_launch(void* const* d_in, const int* in_sizes, int n_in,
                              void* d_out, int out_size)
{
    const float* x      = (const float*)d_in[0];
    const int*   qw     = (const int*)  d_in[1];
    const float* scales = (const float*)d_in[2];
    const float* zeros  = (const float*)d_in[3];
    const float* bias   = (const float*)d_in[4];
    const float* ow     = (const float*)d_in[5];
    const int*   oidx   = (const int*)  d_in[6];
    float* out = (float*)d_out;

    const int INF  = in_sizes[0];          // 8192
    const int OUTF = in_sizes[2];          // 8192
    const int NOUT = in_sizes[6];          // 64
    const int ngroups = INF / 32;          // 256

    cudaMemsetAsync(out, 0, (size_t)out_size * sizeof(float));

    dim3 grid(OUTF / (TPB * CPT), ngroups / NGPB);  // (32, 64) = 2048 blocks
    k_fused<<<grid, TPB>>>(x, qw, scales, zeros, bias, ow, oidx, out,
                           OUTF, INF, NOUT);
}